// round 2
// baseline (speedup 1.0000x reference)
#include <cuda_runtime.h>

#define N_VARS 2048
#define P      8
#define BATCH  4096
#define ROW    (N_VARS * P)      // 16384 floats per x/weight row
#define COLS4  (N_VARS / 4)      // 512 float4 per output row
#define TILE4  256               // float4 columns per block (half of COLS4)
#define ROWS_PER_BLOCK 8

// Fused kernel: per-block gather of the diagonal weight slice into shared
// memory, then a streaming contraction over ROWS_PER_BLOCK batch rows.
//
//   out[b, i] = sum_lag x[b, lag*2048 + i] * weight[i, lag*2048 + i]
__global__ __launch_bounds__(256) void diag_linear_fused_kernel(
    const float*  __restrict__ weight,  // (2048, 16384)
    const float4* __restrict__ x,       // (4096, 16384) as float4
    float4*       __restrict__ out)     // (4096, 2048)  as float4
{
    __shared__ float4 sdiag[P][TILE4];  // 32 KB

    const int ct = blockIdx.x & 1;           // column tile: 0 or 1
    const int rg = blockIdx.x >> 1;          // row group:   0 .. 511
    const int t  = threadIdx.x;               // 0 .. 255
    const int c4 = ct * TILE4 + t;            // float4 column index 0..511
    const int col0 = c4 * 4;                  // base variable index i

    // ---- gather diag slice: diag[lag][i] = weight[i, lag*2048 + i] ----
    #pragma unroll
    for (int lag = 0; lag < P; lag++) {
        float4 d;
        d.x = __ldg(&weight[(size_t)(col0 + 0) * ROW + lag * N_VARS + col0 + 0]);
        d.y = __ldg(&weight[(size_t)(col0 + 1) * ROW + lag * N_VARS + col0 + 1]);
        d.z = __ldg(&weight[(size_t)(col0 + 2) * ROW + lag * N_VARS + col0 + 2]);
        d.w = __ldg(&weight[(size_t)(col0 + 3) * ROW + lag * N_VARS + col0 + 3]);
        sdiag[lag][t] = d;
    }
    __syncthreads();

    // ---- streaming contraction over ROWS_PER_BLOCK batch rows ----
    #pragma unroll 1
    for (int rr = 0; rr < ROWS_PER_BLOCK; rr++) {
        const int r = rg * ROWS_PER_BLOCK + rr;
        const float4* xrow = x + (size_t)r * (ROW / 4);

        float4 acc;
        acc.x = 0.f; acc.y = 0.f; acc.z = 0.f; acc.w = 0.f;

        #pragma unroll
        for (int lag = 0; lag < P; lag++) {
            float4 xv = __ldcs(&xrow[lag * COLS4 + c4]);  // streaming: no reuse
            float4 dv = sdiag[lag][t];
            acc.x = fmaf(xv.x, dv.x, acc.x);
            acc.y = fmaf(xv.y, dv.y, acc.y);
            acc.z = fmaf(xv.z, dv.z, acc.z);
            acc.w = fmaf(xv.w, dv.w, acc.w);
        }
        __stcs(&out[(size_t)r * COLS4 + c4], acc);        // streaming store
    }
}

extern "C" void kernel_launch(void* const* d_in, const int* in_sizes, int n_in,
                              void* d_out, int out_size) {
    const float* x      = (const float*)d_in[0];   // (4096, 16384)
    const float* weight = (const float*)d_in[1];   // (2048, 16384)
    float* out          = (float*)d_out;           // (4096, 2048)

    // 2 column tiles x 512 row groups = 1024 blocks
    const int grid = 2 * (BATCH / ROWS_PER_BLOCK);
    diag_linear_fused_kernel<<<grid, 256>>>(
        weight,
        reinterpret_cast<const float4*>(x),
        reinterpret_cast<float4*>(out));
}

// round 4
// speedup vs baseline: 1.3804x; 1.3804x over previous
#include <cuda_runtime.h>

#define N_VARS 2048
#define P      8
#define BATCH  4096
#define ROW    (N_VARS * P)      // 16384
#define COLS4  (N_VARS / 4)      // 512
#define THREADS 256
#define GATHER_BLOCKS 64         // 64*256 = 16384 diag elements, one per thread

__device__ float g_diag[P * N_VARS];          // gathered diagonal (64 KB)
__device__ unsigned int g_arrive = 0;         // gather blocks completed
__device__ unsigned int g_passed = 0;         // blocks past the spin (for replay reset)

__global__ __launch_bounds__(THREADS) void diag_linear_onekernel(
    const float*  __restrict__ weight,  // (2048, 16384)
    const float4* __restrict__ x,       // (4096, 16384) as float4
    float4*       __restrict__ out)     // (4096, 2048)  as float4
{
    const unsigned int bid = blockIdx.x;
    const int t = threadIdx.x;

    // ---- phase 1: first 64 blocks gather the diagonal ----
    if (bid < GATHER_BLOCKS) {
        int idx = bid * THREADS + t;          // 0 .. 16383
        int lag = idx >> 11;                  // / N_VARS
        int i   = idx & (N_VARS - 1);         // % N_VARS
        g_diag[idx] = __ldg(&weight[(size_t)i * ROW + lag * N_VARS + i]);
        __threadfence();                      // release: publish stores
        __syncthreads();                      // all stores in block done
        if (t == 0) atomicAdd(&g_arrive, 1u);
    }

    // ---- phase 2: wait until the diagonal is published ----
    if (t == 0) {
        volatile unsigned int* f = &g_arrive;
        while (*f < GATHER_BLOCKS) __nanosleep(64);
        __threadfence();                      // acquire: order later reads
        // replay-safe reset: the LAST block through the gate clears counters
        // (fires only after all gridDim.x blocks have passed the spin).
        unsigned int p = atomicAdd(&g_passed, 1u) + 1u;
        if (p == gridDim.x) {
            g_arrive = 0u;
            g_passed = 0u;
            __threadfence();
        }
    }
    __syncthreads();

    // ---- phase 3: streaming body (COHERENT loads for g_diag — it was
    // written this launch, so the __ldg/.nc path is illegal for it) ----
    int tid = bid * THREADS + t;              // 0 .. BATCH*COLS4-1
    int b = tid / COLS4;
    int c = tid - b * COLS4;

    const float4* xrow  = x + (size_t)b * (ROW / 4);
    const float4* diag4 = reinterpret_cast<const float4*>(g_diag);

    float4 acc;
    acc.x = 0.f; acc.y = 0.f; acc.z = 0.f; acc.w = 0.f;

    #pragma unroll
    for (int lag = 0; lag < P; lag++) {
        float4 xv = __ldg(&xrow[lag * COLS4 + c]);   // x is truly read-only
        float4 dv = diag4[lag * COLS4 + c];          // plain coherent ld.global
        acc.x = fmaf(xv.x, dv.x, acc.x);
        acc.y = fmaf(xv.y, dv.y, acc.y);
        acc.z = fmaf(xv.z, dv.z, acc.z);
        acc.w = fmaf(xv.w, dv.w, acc.w);
    }
    out[tid] = acc;
}

extern "C" void kernel_launch(void* const* d_in, const int* in_sizes, int n_in,
                              void* d_out, int out_size) {
    const float* x      = (const float*)d_in[0];   // (4096, 16384)
    const float* weight = (const float*)d_in[1];   // (2048, 16384)
    float* out          = (float*)d_out;           // (4096, 2048)

    const int total = BATCH * COLS4;               // 2,097,152 threads
    diag_linear_onekernel<<<total / THREADS, THREADS>>>(
        weight,
        reinterpret_cast<const float4*>(x),
        reinterpret_cast<float4*>(out));
}

// round 5
// speedup vs baseline: 1.4942x; 1.0825x over previous
#include <cuda_runtime.h>

#define N_VARS 2048
#define P      8
#define BATCH  4096
#define ROW    (N_VARS * P)      // 16384
#define COLS4  (N_VARS / 4)      // 512
#define THREADS 256

// 64 KB scratch for the gathered diagonal: diag[lag*N_VARS + i] = weight[i, lag*N_VARS + i]
__device__ float g_diag[P * N_VARS];

__global__ __launch_bounds__(THREADS) void gather_diag_kernel(
    const float* __restrict__ weight)
{
    int idx = blockIdx.x * THREADS + threadIdx.x;  // 0 .. 16383
    int lag = idx >> 11;                           // / N_VARS
    int i   = idx & (N_VARS - 1);                  // % N_VARS
    g_diag[idx] = __ldg(&weight[(size_t)i * ROW + lag * N_VARS + i]);
}

__global__ __launch_bounds__(THREADS) void diag_linear_kernel(
    const float4* __restrict__ x,    // (4096, 16384) as float4
    float4*       __restrict__ out)  // (4096, 2048)  as float4
{
    int tid = blockIdx.x * THREADS + threadIdx.x;  // 0 .. BATCH*COLS4-1
    int b = tid / COLS4;
    int c = tid - b * COLS4;

    const float4* xrow = x + (size_t)b * (ROW / 4);

    // ---- pre-issue all 8 x loads (independent of the gather kernel) ----
    float4 xv[P];
    #pragma unroll
    for (int lag = 0; lag < P; lag++)
        xv[lag] = __ldg(&xrow[lag * COLS4 + c]);

    // ---- PDL: wait for the gather kernel's completion (memory visible) ----
    cudaGridDependencySynchronize();

    const float4* diag4 = reinterpret_cast<const float4*>(g_diag);
    float4 acc;
    acc.x = 0.f; acc.y = 0.f; acc.z = 0.f; acc.w = 0.f;

    #pragma unroll
    for (int lag = 0; lag < P; lag++) {
        float4 dv = diag4[lag * COLS4 + c];        // L2-hot, 64 KB working set
        acc.x = fmaf(xv[lag].x, dv.x, acc.x);
        acc.y = fmaf(xv[lag].y, dv.y, acc.y);
        acc.z = fmaf(xv[lag].z, dv.z, acc.z);
        acc.w = fmaf(xv[lag].w, dv.w, acc.w);
    }
    out[tid] = acc;
}

extern "C" void kernel_launch(void* const* d_in, const int* in_sizes, int n_in,
                              void* d_out, int out_size) {
    const float* x      = (const float*)d_in[0];   // (4096, 16384)
    const float* weight = (const float*)d_in[1];   // (2048, 16384)
    float* out          = (float*)d_out;           // (4096, 2048)

    // 1) gather diagonal (16384 elements, 64 blocks)
    gather_diag_kernel<<<(P * N_VARS) / THREADS, THREADS>>>(weight);

    // 2) main kernel launched with programmatic dependent launch so its
    //    blocks start (and issue x loads) while the gather is still running.
    cudaLaunchAttribute attrs[1];
    attrs[0].id = cudaLaunchAttributeProgrammaticStreamSerialization;
    attrs[0].val.programmaticStreamSerializationAllowed = 1;

    cudaLaunchConfig_t cfg = {};
    cfg.gridDim  = dim3((BATCH * COLS4) / THREADS, 1, 1);  // 8192 blocks
    cfg.blockDim = dim3(THREADS, 1, 1);
    cfg.dynamicSmemBytes = 0;
    cfg.stream   = 0;           // same (legacy default) stream as <<<>>>
    cfg.attrs    = attrs;
    cfg.numAttrs = 1;

    cudaLaunchKernelEx(&cfg, diag_linear_kernel,
                       reinterpret_cast<const float4*>(x),
                       reinterpret_cast<float4*>(out));
}